// round 10
// baseline (speedup 1.0000x reference)
#include <cuda_runtime.h>
#include <cuda_fp16.h>
#include <cstdint>
#include <cstddef>

#define NDIM 1024
#define KDIM 256
#define BATCH 64   // B*R
#define RDIM 8

// Device-global scratch (no runtime allocation)
__device__ __half g_e[(size_t)BATCH * NDIM * KDIM];    // e = G@Bs, fp16
__device__ __half g_in[(size_t)BATCH * NDIM * KDIM];   // inputs, fp16
__device__ __half g_bsT[(size_t)RDIM * KDIM * KDIM];   // Bs transposed [r][g][f], fp16

__device__ __forceinline__ uint32_t smem_u32(const void* p) {
    uint32_t a;
    asm("{ .reg .u64 t; cvta.to.shared.u64 t, %1; cvt.u32.u64 %0, t; }" : "=r"(a) : "l"(p));
    return a;
}
__device__ __forceinline__ void cp16(uint32_t dst, const void* src) {
    asm volatile("cp.async.cg.shared.global [%0], [%1], 16;" :: "r"(dst), "l"(src));
}

#define LDMX4(r0, r1, r2, r3, addr)                                             \
    asm volatile("ldmatrix.sync.aligned.m8n8.x4.shared.b16 {%0,%1,%2,%3}, [%4];"\
        : "=r"(r0), "=r"(r1), "=r"(r2), "=r"(r3) : "r"(addr))

// m16n8k16 fp16 MMA, fp32 accum
#define MMA_F16(c, a, b)                                                        \
    asm volatile(                                                               \
        "mma.sync.aligned.m16n8k16.row.col.f32.f16.f16.f32 "                    \
        "{%0,%1,%2,%3}, {%4,%5,%6,%7}, {%8,%9}, {%0,%1,%2,%3};"                 \
        : "+f"((c)[0]), "+f"((c)[1]), "+f"((c)[2]), "+f"((c)[3])                \
        : "r"((a)[0]), "r"((a)[1]), "r"((a)[2]), "r"((a)[3]),                   \
          "r"((b)[0]), "r"((b)[1]))

// ---------------------------------------------------------------- pre-passes
__global__ void cvt_f2h(const float* __restrict__ in, __half* __restrict__ out, int n4) {
    int i = blockIdx.x * blockDim.x + threadIdx.x;
    if (i < n4) {
        float4 v = ((const float4*)in)[i];
        ((__half2*)out)[i * 2]     = __floats2half2_rn(v.x, v.y);
        ((__half2*)out)[i * 2 + 1] = __floats2half2_rn(v.z, v.w);
    }
}
__global__ void transpose_bs(const float* __restrict__ Bs, __half* __restrict__ BsT) {
    __shared__ float t[32][33];
    const int r = blockIdx.z;
    const int f0 = blockIdx.x * 32, g0 = blockIdx.y * 32;
    const int tx = threadIdx.x, ty = threadIdx.y;       // 32 x 8
    const float* src = Bs + (size_t)r * KDIM * KDIM;
    __half* dst = BsT + (size_t)r * KDIM * KDIM;
    for (int i = ty; i < 32; i += 8) t[i][tx] = src[(size_t)(f0 + i) * KDIM + g0 + tx];
    __syncthreads();
    for (int i = ty; i < 32; i += 8)
        dst[(size_t)(g0 + i) * KDIM + f0 + tx] = __float2half_rn(t[tx][i]);
}

// ---------------------------------------------------------------- fp16 mma GEMM
// C[128x128 tile] = A[128 x 256] (row-major fp16) @ B[128 x 256]^T (n-major fp16).
// 8 warps (2m x 4n), warp tile 64x32, m16n8k16, ldmatrix, 3-stage cp.async.
// A-fragments double-buffered; XOR-incremental swizzled addressing:
//   addr(k16) = base ^ (k16 << 5), base computed once per chunk.
template<int EPI>   // 0: store fp16 (gemm1 -> g_e) ; 1: sigmoid fp32 (gemm2 -> out)
__global__ __launch_bounds__(256, 2)
void mma_gemm(const __half* __restrict__ Ab, const __half* __restrict__ Bb,
              void* __restrict__ Cb,
              int ldC, int bsel, size_t bStride, size_t cStride) {
    constexpr uint32_t STG = 128u * 128u;       // 16 KB per tile-stage
    constexpr uint32_t B_OFF = 3u * STG;
    constexpr int NCH = KDIM / 64;              // 4 k-chunks

    extern __shared__ char smem[];
    const uint32_t sb = smem_u32(smem);

    const int tid  = threadIdx.x;
    const int warp = tid >> 5, lane = tid & 31;
    const int wm = warp >> 2, wn = warp & 3;    // 2 x 4, warp tile 64x32
    const int tile_n = blockIdx.x, tile_m = blockIdx.y, br = blockIdx.z;

    const __half* A = Ab + (size_t)br * NDIM * KDIM + (size_t)tile_m * 128 * KDIM;
    const __half* B = Bb + (size_t)(bsel ? (br & 7) : br) * bStride + (size_t)tile_n * 128 * KDIM;

    float acc[4][4][4];
    #pragma unroll
    for (int i = 0; i < 4; i++)
        #pragma unroll
        for (int j = 0; j < 4; j++)
            #pragma unroll
            for (int q = 0; q < 4; q++) acc[i][j][q] = 0.f;

    // cp.async: 1024 16B-chunks per tile (128 rows x 8), 4 per thread
    auto load_chunk = [&](int c, int s) {
        const int k0 = c * 64;                  // halves
        const uint32_t ab = sb + (uint32_t)s * STG;
        const uint32_t bb = sb + B_OFF + (uint32_t)s * STG;
        #pragma unroll
        for (int j = 0; j < 4; j++) {
            const int idx = tid + j * 256;
            const int row = idx >> 3, cc = idx & 7;
            const uint32_t off = (uint32_t)(row * 128 + ((cc ^ (row & 7)) << 4));
            cp16(ab + off, A + (size_t)row * KDIM + k0 + cc * 8);
            cp16(bb + off, B + (size_t)row * KDIM + k0 + cc * 8);
        }
        asm volatile("cp.async.commit_group;" ::: "memory");
    };

    load_chunk(0, 0);
    load_chunk(1, 1);

    // ldmatrix lane decomposition
    const int l7 = lane & 7;
    const int arow_in16 = l7 + ((lane >> 3) & 1) * 8;
    const int pa = lane >> 4;                   // A: k-half of 16x16 fragment (bit 0 of cc)
    const int bnt_half = (lane >> 4) & 1;       // B: nt within x4
    const int pb = (lane >> 3) & 1;             // B: k-half (bit 0 of cc)

    const int ar_row = wm * 64 + arow_in16;     // invariant A row base
    const int br_row = wn * 32 + bnt_half * 8 + l7;

    // Per-warp invariant swizzle bases (relative; stage offset added per chunk).
    // addr = stageBase + r*128 + ((p ^ (r&7))<<4), then ^ (k16<<5) per step.
    uint32_t aRel[4], bRel[2];
    #pragma unroll
    for (int mt = 0; mt < 4; mt++) {
        const int r = ar_row + mt * 16;
        aRel[mt] = (uint32_t)(r * 128 + ((pa ^ (r & 7)) << 4));
    }
    #pragma unroll
    for (int q = 0; q < 2; q++) {
        const int r = br_row + q * 16;
        bRel[q] = (uint32_t)(r * 128 + ((pb ^ (r & 7)) << 4));
    }

    #pragma unroll 1
    for (int c = 0; c < NCH; c++) {
        const int s = c - (c / 3) * 3;          // c % 3
        if (c + 2 < NCH) asm volatile("cp.async.wait_group 1;" ::: "memory");
        else             asm volatile("cp.async.wait_group 0;" ::: "memory");
        __syncthreads();

        // issue next-next chunk's global loads before compute
        if (c + 2 < NCH) load_chunk(c + 2, (c + 2) - ((c + 2) / 3) * 3);

        const uint32_t Af = sb + (uint32_t)s * STG;
        const uint32_t Bf = sb + B_OFF + (uint32_t)s * STG;

        uint32_t aB0 = Af + aRel[0], aB1 = Af + aRel[1];
        uint32_t aB2 = Af + aRel[2], aB3 = Af + aRel[3];
        uint32_t bB0 = Bf + bRel[0], bB1 = Bf + bRel[1];

        uint32_t a[2][4][4];                    // double-buffered A fragments

        // prefetch A for k16=0
        LDMX4(a[0][0][0], a[0][0][1], a[0][0][2], a[0][0][3], aB0);
        LDMX4(a[0][1][0], a[0][1][1], a[0][1][2], a[0][1][3], aB1);
        LDMX4(a[0][2][0], a[0][2][1], a[0][2][2], a[0][2][3], aB2);
        LDMX4(a[0][3][0], a[0][3][1], a[0][3][2], a[0][3][3], aB3);

        #pragma unroll
        for (int k16 = 0; k16 < 4; k16++) {
            const int cur = k16 & 1;
            const uint32_t kx  = (uint32_t)(k16 << 5);
            const uint32_t kxn = (uint32_t)((k16 + 1) << 5);
            uint32_t b[4][2];
            // B for this step (single XOR per address)
            LDMX4(b[0][0], b[0][1], b[1][0], b[1][1], bB0 ^ kx);
            LDMX4(b[2][0], b[2][1], b[3][0], b[3][1], bB1 ^ kx);
            // A for next step
            if (k16 < 3) {
                LDMX4(a[cur ^ 1][0][0], a[cur ^ 1][0][1], a[cur ^ 1][0][2], a[cur ^ 1][0][3], aB0 ^ kxn);
                LDMX4(a[cur ^ 1][1][0], a[cur ^ 1][1][1], a[cur ^ 1][1][2], a[cur ^ 1][1][3], aB1 ^ kxn);
                LDMX4(a[cur ^ 1][2][0], a[cur ^ 1][2][1], a[cur ^ 1][2][2], a[cur ^ 1][2][3], aB2 ^ kxn);
                LDMX4(a[cur ^ 1][3][0], a[cur ^ 1][3][1], a[cur ^ 1][3][2], a[cur ^ 1][3][3], aB3 ^ kxn);
            }
            #pragma unroll
            for (int mt = 0; mt < 4; mt++)
                #pragma unroll
                for (int nt = 0; nt < 4; nt++)
                    MMA_F16(acc[mt][nt], a[cur][mt], b[nt]);
        }
    }

    // Epilogue: thread holds (r,c),(r,c+1),(r+8,c),(r+8,c+1) per (mt,nt)
    const int rbase = wm * 64 + (lane >> 2);
    const int cbase = wn * 32 + 2 * (lane & 3);
    if (EPI == 0) {
        __half* C = (__half*)Cb + (size_t)br * cStride +
                    (size_t)(tile_m * 128) * ldC + tile_n * 128;
        #pragma unroll
        for (int mt = 0; mt < 4; mt++) {
            const int r = rbase + mt * 16;
            #pragma unroll
            for (int nt = 0; nt < 4; nt++) {
                const int cc = cbase + nt * 8;
                *(__half2*)(C + (size_t)r * ldC + cc) =
                    __floats2half2_rn(acc[mt][nt][0], acc[mt][nt][1]);
                *(__half2*)(C + (size_t)(r + 8) * ldC + cc) =
                    __floats2half2_rn(acc[mt][nt][2], acc[mt][nt][3]);
            }
        }
    } else {
        float* C = (float*)Cb + (size_t)br * cStride +
                   (size_t)(tile_m * 128) * ldC + tile_n * 128;
        #pragma unroll
        for (int mt = 0; mt < 4; mt++) {
            const int r = rbase + mt * 16;
            #pragma unroll
            for (int nt = 0; nt < 4; nt++) {
                const int cc = cbase + nt * 8;
                float2 v0, v1;
                v0.x = 1.f / (1.f + __expf(-acc[mt][nt][0]));
                v0.y = 1.f / (1.f + __expf(-acc[mt][nt][1]));
                v1.x = 1.f / (1.f + __expf(-acc[mt][nt][2]));
                v1.y = 1.f / (1.f + __expf(-acc[mt][nt][3]));
                *(float2*)(C + (size_t)r * ldC + cc) = v0;
                *(float2*)(C + (size_t)(r + 8) * ldC + cc) = v1;
            }
        }
    }
}

// ---------------------------------------------------------------- launch
extern "C" void kernel_launch(void* const* d_in, const int* in_sizes, int n_in,
                              void* d_out, int out_size) {
    const float* inputs = (const float*)d_in[0];   // [8,8,1024,256]
    const float* Bw     = (const float*)d_in[1];   // [8,256,256]
    float* out          = (float*)d_out;           // [8,8,1024,1024]

    __half *pe, *pin, *pbsT;
    cudaGetSymbolAddress((void**)&pe,   g_e);
    cudaGetSymbolAddress((void**)&pin,  g_in);
    cudaGetSymbolAddress((void**)&pbsT, g_bsT);

    // fp16 pre-passes
    const int n4i = (BATCH * NDIM * KDIM) / 4;
    cvt_f2h<<<(n4i + 255) / 256, 256>>>(inputs, pin, n4i);
    transpose_bs<<<dim3(8, 8, 8), dim3(32, 8)>>>(Bw, pbsT);

    const size_t smemB = 6 * 128 * 128;   // 3 stages x (A 16K + B 16K) = 96 KB
    cudaFuncSetAttribute(mma_gemm<0>, cudaFuncAttributeMaxDynamicSharedMemorySize, (int)smemB);
    cudaFuncSetAttribute(mma_gemm<1>, cudaFuncAttributeMaxDynamicSharedMemorySize, (int)smemB);

    // GEMM1: e[1024,256] = in @ bsT^T  (fp16 out)
    mma_gemm<0><<<dim3(KDIM / 128, NDIM / 128, BATCH), 256, smemB>>>(
        pin, pbsT, pe,
        KDIM, /*bsel=*/1, (size_t)KDIM * KDIM, (size_t)NDIM * KDIM);

    // GEMM2: scores = e @ in^T ; sigmoid (fp32 out)
    mma_gemm<1><<<dim3(NDIM / 128, NDIM / 128, BATCH), 256, smemB>>>(
        pe, pin, out,
        NDIM, /*bsel=*/0, (size_t)NDIM * KDIM, (size_t)NDIM * NDIM);
}

// round 11
// speedup vs baseline: 1.2609x; 1.2609x over previous
#include <cuda_runtime.h>
#include <cuda_fp16.h>
#include <cstdint>
#include <cstddef>

#define NDIM 1024
#define KDIM 256
#define BATCH 64   // B*R
#define RDIM 8

// Chunked+swizzled scratch layouts (row pitch 128 B, 16B units XOR-swizzled by row&7):
//   g_in, g_e : [br][kc=4][row=1024][64 halves]   (chunk = 128 KB, CTA slice 16 KB)
//   g_bsT     : [r][fc=4][g=256][64 halves]       (chunk = 32 KB,  CTA slice 16 KB)
__device__ __half g_e[(size_t)BATCH * NDIM * KDIM];
__device__ __half g_in[(size_t)BATCH * NDIM * KDIM];
__device__ __half g_bsT[(size_t)RDIM * KDIM * KDIM];

__device__ __forceinline__ uint32_t smem_u32(const void* p) {
    uint32_t a;
    asm("{ .reg .u64 t; cvta.to.shared.u64 t, %1; cvt.u32.u64 %0, t; }" : "=r"(a) : "l"(p));
    return a;
}
__device__ __forceinline__ void bulk_g2s(uint32_t dst, const void* src, uint32_t bytes,
                                         uint32_t mbar) {
    asm volatile(
        "cp.async.bulk.shared::cta.global.mbarrier::complete_tx::bytes [%0], [%1], %2, [%3];"
        :: "r"(dst), "l"(src), "r"(bytes), "r"(mbar) : "memory");
}
__device__ __forceinline__ void mbar_init(uint32_t a, uint32_t cnt) {
    asm volatile("mbarrier.init.shared.b64 [%0], %1;" :: "r"(a), "r"(cnt) : "memory");
}
__device__ __forceinline__ void mbar_expect_tx(uint32_t a, uint32_t bytes) {
    asm volatile("mbarrier.arrive.expect_tx.shared.b64 _, [%0], %1;"
                 :: "r"(a), "r"(bytes) : "memory");
}
__device__ __forceinline__ void mbar_wait(uint32_t a, uint32_t parity) {
    asm volatile(
        "{\n\t.reg .pred P;\n\tWL%=:\n\t"
        "mbarrier.try_wait.parity.shared.b64 P, [%0], %1;\n\t"
        "@P bra.uni WD%=;\n\tbra.uni WL%=;\n\tWD%=:\n\t}"
        :: "r"(a), "r"(parity) : "memory");
}
__device__ __forceinline__ float sigmoid_fast(float x) {
    float t;
    asm("tanh.approx.f32 %0, %1;" : "=f"(t) : "f"(x * 0.5f));
    return fmaf(t, 0.5f, 0.5f);
}

#define LDMX4(r0, r1, r2, r3, addr)                                             \
    asm volatile("ldmatrix.sync.aligned.m8n8.x4.shared.b16 {%0,%1,%2,%3}, [%4];"\
        : "=r"(r0), "=r"(r1), "=r"(r2), "=r"(r3) : "r"(addr))

#define MMA_F16(c, a, b)                                                        \
    asm volatile(                                                               \
        "mma.sync.aligned.m16n8k16.row.col.f32.f16.f16.f32 "                    \
        "{%0,%1,%2,%3}, {%4,%5,%6,%7}, {%8,%9}, {%0,%1,%2,%3};"                 \
        : "+f"((c)[0]), "+f"((c)[1]), "+f"((c)[2]), "+f"((c)[3])                \
        : "r"((a)[0]), "r"((a)[1]), "r"((a)[2]), "r"((a)[3]),                   \
          "r"((b)[0]), "r"((b)[1]))

// ---------------------------------------------------------------- pre-passes
// fp32 -> fp16 into chunked+swizzled layout. One thread = one 16B unit.
__global__ void cvt_f2h_chunked(const float* __restrict__ in, __half* __restrict__ out) {
    const int t = blockIdx.x * blockDim.x + threadIdx.x;   // 64*1024*32 threads
    const int u32 = t & 31;            // unit index within 256-half row
    const int row = t >> 5;            // br*1024 + n
    const int n  = row & 1023;
    const int kc = u32 >> 3, u = u32 & 7;
    const float* src = in + ((size_t)row * 256 + kc * 64 + u * 8);
    float4 v0 = *(const float4*)src;
    float4 v1 = *(const float4*)(src + 4);
    uint4 h;
    h.x = __half2_raw(__floats2half2_rn(v0.x, v0.y)).x |
          ((uint32_t)__half2_raw(__floats2half2_rn(v0.x, v0.y)).y << 16);
    // build via half2 stores instead (simpler & correct):
    __half2 hh[4] = { __floats2half2_rn(v0.x, v0.y), __floats2half2_rn(v0.z, v0.w),
                      __floats2half2_rn(v1.x, v1.y), __floats2half2_rn(v1.z, v1.w) };
    const size_t rowOut = ((size_t)(row >> 10) * 4 + kc) * 1024 + n;
    char* dst = (char*)out + rowOut * 128 + (size_t)((u ^ (n & 7)) << 4);
    *(uint4*)dst = *(uint4*)hh;
    (void)h;
}
// Bs[r][f][g] -> bsT chunked+swizzled: [r][f/64][g][64]
__global__ void transpose_bs(const float* __restrict__ Bs, __half* __restrict__ BsT) {
    __shared__ float t[32][33];
    const int r = blockIdx.z;
    const int f0 = blockIdx.x * 32, g0 = blockIdx.y * 32;
    const int tx = threadIdx.x, ty = threadIdx.y;       // 32 x 8
    const float* src = Bs + (size_t)r * KDIM * KDIM;
    for (int i = ty; i < 32; i += 8) t[i][tx] = src[(size_t)(f0 + i) * KDIM + g0 + tx];
    __syncthreads();
    char* base = (char*)BsT;
    for (int i = ty; i < 32; i += 8) {
        const int g = g0 + i, f = f0 + tx;
        const size_t rowOut = ((size_t)r * 4 + (f >> 6)) * 256 + g;
        const uint32_t off = (uint32_t)((((f >> 3) & 7) ^ (g & 7)) << 4) + (f & 7) * 2;
        *(__half*)(base + rowOut * 128 + off) = __float2half_rn(t[tx][i]);
    }
}

// ---------------------------------------------------------------- fp16 mma GEMM
// C tile 128x128; A/B delivered per-chunk as contiguous pre-swizzled 16KB blocks
// via cp.async.bulk + mbarrier. 8 warps (2m x 4n), warp tile 64x32, m16n8k16.
template<int EPI>   // 0: store fp16 chunked (gemm1 -> g_e) ; 1: sigmoid fp32 (gemm2 -> out)
__global__ __launch_bounds__(256, 2)
void mma_gemm(const char* __restrict__ Ab, const char* __restrict__ Bb,
              void* __restrict__ Cb,
              int ldC, int bsel, size_t aCS, size_t bCS, size_t cStride) {
    constexpr uint32_t STG = 16384u;
    constexpr uint32_t B_OFF = 3u * STG;
    constexpr uint32_t MB_OFF = 6u * STG;
    constexpr int NCH = 4;

    extern __shared__ char smem[];
    const uint32_t sb = smem_u32(smem);

    const int tid  = threadIdx.x;
    const int warp = tid >> 5, lane = tid & 31;
    const int wm = warp >> 2, wn = warp & 3;
    const int tile_n = blockIdx.x, tile_m = blockIdx.y, br = blockIdx.z;

    const char* Asrc = Ab + (size_t)br * (NCH * aCS) + (size_t)tile_m * STG;
    const char* Bsrc = Bb + (size_t)(bsel ? (br & 7) : br) * (NCH * bCS) + (size_t)tile_n * STG;

    if (tid == 0) {
        mbar_init(sb + MB_OFF,      1);
        mbar_init(sb + MB_OFF + 8,  1);
        mbar_init(sb + MB_OFF + 16, 1);
        asm volatile("fence.proxy.async.shared::cta;" ::: "memory");
    }
    __syncthreads();

    auto issue = [&](int c) {
        const uint32_t s = (uint32_t)(c - (c / 3) * 3);
        const uint32_t mb = sb + MB_OFF + s * 8;
        mbar_expect_tx(mb, 2 * STG);
        bulk_g2s(sb + s * STG,         Asrc + (size_t)c * aCS, STG, mb);
        bulk_g2s(sb + B_OFF + s * STG, Bsrc + (size_t)c * bCS, STG, mb);
    };
    if (tid == 0) { issue(0); issue(1); }

    float acc[4][4][4];
    #pragma unroll
    for (int i = 0; i < 4; i++)
        #pragma unroll
        for (int j = 0; j < 4; j++)
            #pragma unroll
            for (int q = 0; q < 4; q++) acc[i][j][q] = 0.f;

    // ldmatrix lane decomposition (pre-swizzled smem, same XOR addressing)
    const int l7 = lane & 7;
    const int arow_in16 = l7 + ((lane >> 3) & 1) * 8;
    const int pa = lane >> 4;
    const int bnt_half = (lane >> 4) & 1;
    const int pb = (lane >> 3) & 1;
    const int ar_row = wm * 64 + arow_in16;
    const int br_row = wn * 32 + bnt_half * 8 + l7;

    uint32_t aRel[4], bRel[2];
    #pragma unroll
    for (int mt = 0; mt < 4; mt++) {
        const int r = ar_row + mt * 16;
        aRel[mt] = (uint32_t)(r * 128 + ((pa ^ (r & 7)) << 4));
    }
    #pragma unroll
    for (int q = 0; q < 2; q++) {
        const int r = br_row + q * 16;
        bRel[q] = (uint32_t)(r * 128 + ((pb ^ (r & 7)) << 4));
    }

    #pragma unroll 1
    for (int c = 0; c < NCH; c++) {
        const int s = c - (c / 3) * 3;
        mbar_wait(sb + MB_OFF + (uint32_t)s * 8, (uint32_t)((c / 3) & 1));
        __syncthreads();
        if (c + 2 < NCH && tid == 0) issue(c + 2);

        const uint32_t Af = sb + (uint32_t)s * STG;
        const uint32_t Bf = sb + B_OFF + (uint32_t)s * STG;
        const uint32_t aB0 = Af + aRel[0], aB1 = Af + aRel[1];
        const uint32_t aB2 = Af + aRel[2], aB3 = Af + aRel[3];
        const uint32_t bB0 = Bf + bRel[0], bB1 = Bf + bRel[1];

        uint32_t a[2][4][4];
        LDMX4(a[0][0][0], a[0][0][1], a[0][0][2], a[0][0][3], aB0);
        LDMX4(a[0][1][0], a[0][1][1], a[0][1][2], a[0][1][3], aB1);
        LDMX4(a[0][2][0], a[0][2][1], a[0][2][2], a[0][2][3], aB2);
        LDMX4(a[0][3][0], a[0][3][1], a[0][3][2], a[0][3][3], aB3);

        #pragma unroll
        for (int k16 = 0; k16 < 4; k16++) {
            const int cur = k16 & 1;
            const uint32_t kx  = (uint32_t)(k16 << 5);
            const uint32_t kxn = (uint32_t)((k16 + 1) << 5);
            uint32_t b[4][2];
            LDMX4(b[0][0], b[0][1], b[1][0], b[1][1], bB0 ^ kx);
            LDMX4(b[2][0], b[2][1], b[3][0], b[3][1], bB1 ^ kx);
            if (k16 < 3) {
                LDMX4(a[cur ^ 1][0][0], a[cur ^ 1][0][1], a[cur ^ 1][0][2], a[cur ^ 1][0][3], aB0 ^ kxn);
                LDMX4(a[cur ^ 1][1][0], a[cur ^ 1][1][1], a[cur ^ 1][1][2], a[cur ^ 1][1][3], aB1 ^ kxn);
                LDMX4(a[cur ^ 1][2][0], a[cur ^ 1][2][1], a[cur ^ 1][2][2], a[cur ^ 1][2][3], aB2 ^ kxn);
                LDMX4(a[cur ^ 1][3][0], a[cur ^ 1][3][1], a[cur ^ 1][3][2], a[cur ^ 1][3][3], aB3 ^ kxn);
            }
            #pragma unroll
            for (int mt = 0; mt < 4; mt++)
                #pragma unroll
                for (int nt = 0; nt < 4; nt++)
                    MMA_F16(acc[mt][nt], a[cur][mt], b[nt]);
        }
    }

    // Epilogue
    const int rbase = wm * 64 + (lane >> 2);
    const int cbase = wn * 32 + 2 * (lane & 3);
    if (EPI == 0) {
        // write e in chunked+swizzled layout
        char* base = (char*)Cb;
        #pragma unroll
        for (int mt = 0; mt < 4; mt++) {
            const int rl = rbase + mt * 16;                    // local row 0..127
            const int nrow = tile_m * 128 + rl;                // global n
            #pragma unroll
            for (int nt = 0; nt < 4; nt++) {
                const int gl = tile_n * 128 + cbase + nt * 8;  // global g col
                const int gc = gl >> 6;
                const uint32_t u = (uint32_t)((gl >> 3) & 7);
                const uint32_t inb = (uint32_t)((gl & 7) * 2);
                const size_t row0 = ((size_t)br * 4 + gc) * 1024 + nrow;
                const uint32_t sw = ((u ^ (uint32_t)(nrow & 7)) << 4) + inb;
                *(__half2*)(base + row0 * 128 + sw) =
                    __floats2half2_rn(acc[mt][nt][0], acc[mt][nt][1]);
                *(__half2*)(base + (row0 + 8) * 128 + sw) =
                    __floats2half2_rn(acc[mt][nt][2], acc[mt][nt][3]);
            }
        }
    } else {
        float* C = (float*)Cb + (size_t)br * cStride +
                   (size_t)(tile_m * 128) * ldC + tile_n * 128;
        #pragma unroll
        for (int mt = 0; mt < 4; mt++) {
            const int r = rbase + mt * 16;
            #pragma unroll
            for (int nt = 0; nt < 4; nt++) {
                const int cc = cbase + nt * 8;
                float2 v0, v1;
                v0.x = sigmoid_fast(acc[mt][nt][0]);
                v0.y = sigmoid_fast(acc[mt][nt][1]);
                v1.x = sigmoid_fast(acc[mt][nt][2]);
                v1.y = sigmoid_fast(acc[mt][nt][3]);
                *(float2*)(C + (size_t)r * ldC + cc) = v0;
                *(float2*)(C + (size_t)(r + 8) * ldC + cc) = v1;
            }
        }
    }
}

// ---------------------------------------------------------------- launch
extern "C" void kernel_launch(void* const* d_in, const int* in_sizes, int n_in,
                              void* d_out, int out_size) {
    const float* inputs = (const float*)d_in[0];   // [8,8,1024,256]
    const float* Bw     = (const float*)d_in[1];   // [8,256,256]
    float* out          = (float*)d_out;           // [8,8,1024,1024]

    __half *pe, *pin, *pbsT;
    cudaGetSymbolAddress((void**)&pe,   g_e);
    cudaGetSymbolAddress((void**)&pin,  g_in);
    cudaGetSymbolAddress((void**)&pbsT, g_bsT);

    // pre-passes into chunked+swizzled layouts
    const int nthr = BATCH * NDIM * 32;            // one 16B unit per thread
    cvt_f2h_chunked<<<nthr / 256, 256>>>(inputs, pin);
    transpose_bs<<<dim3(8, 8, 8), dim3(32, 8)>>>(Bw, pbsT);

    const size_t smemB = 6 * 16384 + 64;
    cudaFuncSetAttribute(mma_gemm<0>, cudaFuncAttributeMaxDynamicSharedMemorySize, (int)smemB);
    cudaFuncSetAttribute(mma_gemm<1>, cudaFuncAttributeMaxDynamicSharedMemorySize, (int)smemB);

    // GEMM1: e = in @ bsT^T   (A chunk stride 128KB, B chunk stride 32KB)
    mma_gemm<0><<<dim3(KDIM / 128, NDIM / 128, BATCH), 256, smemB>>>(
        (const char*)pin, (const char*)pbsT, pe,
        0, /*bsel=*/1, (size_t)1024 * 128, (size_t)256 * 128, 0);

    // GEMM2: scores = e @ in^T ; sigmoid
    mma_gemm<1><<<dim3(NDIM / 128, NDIM / 128, BATCH), 256, smemB>>>(
        (const char*)pe, (const char*)pin, out,
        NDIM, /*bsel=*/0, (size_t)1024 * 128, (size_t)1024 * 128, (size_t)NDIM * NDIM);
}